// round 15
// baseline (speedup 1.0000x reference)
#include <cuda_runtime.h>
#include <cuda_bf16.h>
#include <math.h>
#include <stdint.h>

#define T_TOK 2048
#define DDIM  2048
#define FDIM  4096
#define NEXP  8

// ---------- gu geometry: M=256 tile, KC 32, NSTG 3 ----------
#define GU_NSTG 3
#define GU_KC   32
#define GU_AST  80
#define GU_BST  272
#define GU_ASTG (256 * GU_AST)                  // 20480
#define GU_BSTG (GU_KC * GU_BST)                // 8704
#define GU_AHI  0
#define GU_ALO  (GU_NSTG * GU_ASTG)             // 61440
#define GU_BHI  (2 * GU_NSTG * GU_ASTG)         // 122880
#define GU_BLO  (GU_BHI + GU_NSTG * GU_BSTG)    // 148992
#define SMEM_GU (GU_BLO + GU_NSTG * GU_BSTG)    // 175104

// ---------- dn geometry: M=256 tile, KC 32, NSTG 3 ----------
#define DN_NSTG 3
#define DN_KC   32
#define DN_AST  80
#define DN_BST  144
#define DN_ASTG (256 * DN_AST)                  // 20480
#define DN_BSTG (DN_KC * DN_BST)                // 4608
#define DN_AHI  0
#define DN_ALO  (DN_NSTG * DN_ASTG)
#define DN_BHI  (2 * DN_NSTG * DN_ASTG)
#define DN_BLO  (DN_BHI + DN_NSTG * DN_BSTG)
#define SMEM_DN (DN_BLO + DN_NSTG * DN_BSTG)    // 150528

#define WGU_ELEMS ((size_t)NEXP * DDIM * FDIM)
#define WD_ELEMS  ((size_t)NEXP * FDIM * DDIM)

// ---- static scratch ----
__device__ int   g_cnt[NEXP];
__device__ int   g_eid[T_TOK];
__device__ float g_w[T_TOK];
__device__ int   g_list[NEXP * T_TOK];
__device__ __align__(16) __nv_bfloat16 g_xhi[(size_t)T_TOK * DDIM];
__device__ __align__(16) __nv_bfloat16 g_xlo[(size_t)T_TOK * DDIM];
__device__ __align__(16) __nv_bfloat16 g_hhi[(size_t)T_TOK * FDIM];
__device__ __align__(16) __nv_bfloat16 g_hlo[(size_t)T_TOK * FDIM];
__device__ __align__(16) __nv_bfloat16 g_hshi[(size_t)T_TOK * FDIM];
__device__ __align__(16) __nv_bfloat16 g_hslo[(size_t)T_TOK * FDIM];
__device__ __align__(16) __nv_bfloat16 g_wghi[(size_t)NEXP * DDIM * FDIM];
__device__ __align__(16) __nv_bfloat16 g_wglo[(size_t)NEXP * DDIM * FDIM];
__device__ __align__(16) __nv_bfloat16 g_wuhi[(size_t)NEXP * DDIM * FDIM];
__device__ __align__(16) __nv_bfloat16 g_wulo[(size_t)NEXP * DDIM * FDIM];
__device__ __align__(16) __nv_bfloat16 g_wdhi[(size_t)NEXP * FDIM * DDIM];
__device__ __align__(16) __nv_bfloat16 g_wdlo[(size_t)NEXP * FDIM * DDIM];
__device__ __align__(16) __nv_bfloat16 g_wsghi[(size_t)DDIM * FDIM];
__device__ __align__(16) __nv_bfloat16 g_wsglo[(size_t)DDIM * FDIM];
__device__ __align__(16) __nv_bfloat16 g_wsuhi[(size_t)DDIM * FDIM];
__device__ __align__(16) __nv_bfloat16 g_wsulo[(size_t)DDIM * FDIM];
__device__ __align__(16) __nv_bfloat16 g_wsdhi[(size_t)FDIM * DDIM];
__device__ __align__(16) __nv_bfloat16 g_wsdlo[(size_t)FDIM * DDIM];

// ---- helpers ----
__device__ __forceinline__ uint32_t smem_u32(const void* p) {
    uint32_t a;
    asm("{ .reg .u64 t; cvta.to.shared.u64 t, %1; cvt.u32.u64 %0, t; }"
        : "=r"(a) : "l"(p));
    return a;
}

__device__ __forceinline__ void cpa16(uint32_t dst, const void* src, int srcsz) {
    asm volatile("cp.async.cg.shared.global [%0], [%1], 16, %2;"
                 :: "r"(dst), "l"(src), "r"(srcsz) : "memory");
}
#define CP_COMMIT() asm volatile("cp.async.commit_group;" ::: "memory")

#define MMA_BF16(d, a, b) \
    asm volatile("mma.sync.aligned.m16n8k16.row.col.f32.bf16.bf16.f32 " \
        "{%0,%1,%2,%3}, {%4,%5,%6,%7}, {%8,%9}, {%0,%1,%2,%3};" \
        : "+f"((d)[0]), "+f"((d)[1]), "+f"((d)[2]), "+f"((d)[3]) \
        : "r"((a)[0]), "r"((a)[1]), "r"((a)[2]), "r"((a)[3]), \
          "r"((b)[0]), "r"((b)[1]))

#define LDSM_X4(r0, r1, r2, r3, addr) \
    asm volatile("ldmatrix.sync.aligned.m8n8.x4.shared.b16 {%0,%1,%2,%3}, [%4];" \
        : "=r"(r0), "=r"(r1), "=r"(r2), "=r"(r3) : "r"(addr))

#define LDSM_X4T(r0, r1, r2, r3, addr) \
    asm volatile("ldmatrix.sync.aligned.m8n8.x4.trans.shared.b16 {%0,%1,%2,%3}, [%4];" \
        : "=r"(r0), "=r"(r1), "=r"(r2), "=r"(r3) : "r"(addr))

__device__ __forceinline__ void bf16_split2(float2 f, uint32_t& hi, uint32_t& lo) {
    uint32_t h;
    asm("cvt.rn.bf16x2.f32 %0, %1, %2;" : "=r"(h) : "f"(f.y), "f"(f.x));
    float hx = __uint_as_float(h << 16);
    float hy = __uint_as_float(h & 0xffff0000u);
    asm("cvt.rn.bf16x2.f32 %0, %1, %2;" : "=r"(lo) : "f"(f.y - hy), "f"(f.x - hx));
    hi = h;
}

__device__ __forceinline__ float silu_f(float g) {
    return g / (1.f + __expf(-g));
}

__device__ __forceinline__ void conv8(const float* src, __nv_bfloat16* dhi,
                                      __nv_bfloat16* dlo, size_t off) {
    float4 a = *(const float4*)(src + off);
    float4 b = *(const float4*)(src + off + 4);
    uint32_t h0, l0, h1, l1, h2, l2, h3, l3;
    bf16_split2(make_float2(a.x, a.y), h0, l0);
    bf16_split2(make_float2(a.z, a.w), h1, l1);
    bf16_split2(make_float2(b.x, b.y), h2, l2);
    bf16_split2(make_float2(b.z, b.w), h3, l3);
    *(uint4*)(dhi + off) = make_uint4(h0, h1, h2, h3);
    *(uint4*)(dlo + off) = make_uint4(l0, l1, l2, l3);
}

// ---- routing / setup ----
__global__ void zero_counts() {
    if (threadIdx.x < NEXP) g_cnt[threadIdx.x] = 0;
}

__global__ void router_kernel(const float* __restrict__ x,
                              const float* __restrict__ rw) {
    int t = blockIdx.x * blockDim.y + threadIdx.y;
    if (t >= T_TOK) return;
    int lane = threadIdx.x;
    float acc[NEXP];
#pragma unroll
    for (int e = 0; e < NEXP; e++) acc[e] = 0.f;
    const float* xr = x + (size_t)t * DDIM;
    for (int d = lane; d < DDIM; d += 32) {
        float xv = xr[d];
        const float4* r = (const float4*)(rw + (size_t)d * NEXP);
        float4 r0 = r[0], r1 = r[1];
        acc[0] += xv * r0.x; acc[1] += xv * r0.y;
        acc[2] += xv * r0.z; acc[3] += xv * r0.w;
        acc[4] += xv * r1.x; acc[5] += xv * r1.y;
        acc[6] += xv * r1.z; acc[7] += xv * r1.w;
    }
#pragma unroll
    for (int off = 16; off > 0; off >>= 1)
#pragma unroll
        for (int e = 0; e < NEXP; e++)
            acc[e] += __shfl_down_sync(0xffffffffu, acc[e], off);
    if (lane == 0) {
        int best = 0; float bv = acc[0];
#pragma unroll
        for (int e = 1; e < NEXP; e++)
            if (acc[e] > bv) { bv = acc[e]; best = e; }
        g_eid[t] = best;
        g_w[t]   = 1.f / (1.f + expf(-bv));
    }
}

__global__ void scatter_kernel() {
    int t = blockIdx.x * blockDim.x + threadIdx.x;
    if (t < T_TOK) {
        int e = g_eid[t];
        int p = atomicAdd(&g_cnt[e], 1);
        g_list[e * T_TOK + p] = t;
    }
}

__global__ void convert_x(const float* __restrict__ x) {
    size_t off = ((size_t)blockIdx.x * 256 + threadIdx.x) * 8;
    conv8(x, g_xhi, g_xlo, off);
}

__global__ void __launch_bounds__(256)
convert_wsgu(const float* __restrict__ wsg, const float* __restrict__ wsu) {
    size_t off = ((size_t)blockIdx.x * 256 + threadIdx.x) * 8;
    const size_t N = (size_t)DDIM * FDIM;
    if (off < N) conv8(wsg, g_wsghi, g_wsglo, off);
    else         conv8(wsu, g_wsuhi, g_wsulo, off - N);
}

__global__ void zero_out(float4* out) {
    out[(size_t)blockIdx.x * 256 + threadIdx.x] = make_float4(0.f, 0.f, 0.f, 0.f);
}

// ================= gate+up GEMM (M=256 tile) =================
template<bool SHARED>
__global__ void __launch_bounds__(256)
gu_kernel(const float* __restrict__ cv0, const float* __restrict__ cv1) {
    int tid = threadIdx.x;

    if (blockIdx.y >= 64) {
        if (SHARED) {
            int cid = (blockIdx.y - 64) * 8 + blockIdx.x;       // 0..2047
            size_t base = (size_t)cid * 65536;
#pragma unroll 4
            for (int it = 0; it < 32; it++) {
                size_t e0 = base + (size_t)it * 2048 + (size_t)tid * 8;
                if (e0 < WGU_ELEMS) conv8(cv0, g_wghi, g_wglo, e0);
                else                conv8(cv1, g_wuhi, g_wulo, e0 - WGU_ELEMS);
            }
        } else {
            int cid = (blockIdx.y - 64) + 18 * (blockIdx.x + 8 * blockIdx.z); // 0..1151
            size_t base = (size_t)cid * 65536;
#pragma unroll 4
            for (int it = 0; it < 32; it++) {
                size_t e0 = base + (size_t)it * 2048 + (size_t)tid * 8;
                if (e0 < WD_ELEMS) conv8(cv0, g_wdhi, g_wdlo, e0);
                else               conv8(cv1, g_wsdhi, g_wsdlo, e0 - WD_ELEMS);
            }
        }
        return;
    }

    int e   = SHARED ? 0 : blockIdx.z;
    int cnt = SHARED ? T_TOK : g_cnt[e];
    int m0  = blockIdx.x * 256;
    if (m0 >= cnt) return;
    int n0  = blockIdx.y * 64;

    const __nv_bfloat16* bgh = SHARED ? g_wsghi : g_wghi + (size_t)e * DDIM * FDIM;
    const __nv_bfloat16* bgl = SHARED ? g_wsglo : g_wglo + (size_t)e * DDIM * FDIM;
    const __nv_bfloat16* buh = SHARED ? g_wsuhi : g_wuhi + (size_t)e * DDIM * FDIM;
    const __nv_bfloat16* bul = SHARED ? g_wsulo : g_wulo + (size_t)e * DDIM * FDIM;
    __nv_bfloat16* hhi = SHARED ? g_hshi : g_hhi;
    __nv_bfloat16* hlo = SHARED ? g_hslo : g_hlo;

    extern __shared__ char dyn[];
    __shared__ int toks[256];
    {
        int m = m0 + tid;
        toks[tid] = (m < cnt) ? (SHARED ? m : g_list[e * T_TOK + m]) : -1;
    }
    __syncthreads();

    uint32_t smb = smem_u32(dyn);

    // A loads: 256 rows x 4 chunks of 16B per array -> 1024 chunks, 4/thread
    const __nv_bfloat16* ahsrc[4];
    const __nv_bfloat16* alsrc[4];
    int apred[4];
    uint32_t adst[4];
#pragma unroll
    for (int i = 0; i < 4; i++) {
        int s = tid + 256 * i;
        int row = s >> 2, chk = s & 3;
        int tk = toks[row];
        apred[i] = (tk >= 0) ? 16 : 0;
        size_t off = (tk >= 0) ? ((size_t)tk * DDIM + chk * 8) : 0;
        ahsrc[i] = g_xhi + off;
        alsrc[i] = g_xlo + off;
        adst[i]  = row * GU_AST + chk * 16;
    }
    // B loads: 32 k-rows x 16 chunks -> 512 chunks, 2/thread
    const __nv_bfloat16* bhsrc[2];
    const __nv_bfloat16* blsrc[2];
    uint32_t bdst[2];
#pragma unroll
    for (int i = 0; i < 2; i++) {
        int s = tid + 256 * i;
        int brow = s >> 4, bchk = s & 15;
        size_t boff = (size_t)brow * FDIM + n0 + (bchk & 7) * 8;
        bhsrc[i] = ((bchk < 8) ? bgh : buh) + boff;
        blsrc[i] = ((bchk < 8) ? bgl : bul) + boff;
        bdst[i]  = brow * GU_BST + bchk * 16;
    }

    auto load_stage = [&](int kc, int st) {
        int k0 = kc * GU_KC;
#pragma unroll
        for (int i = 0; i < 4; i++) {
            cpa16(smb + GU_AHI + st * GU_ASTG + adst[i], ahsrc[i] + k0, apred[i]);
            cpa16(smb + GU_ALO + st * GU_ASTG + adst[i], alsrc[i] + k0, apred[i]);
        }
#pragma unroll
        for (int i = 0; i < 2; i++) {
            cpa16(smb + GU_BHI + st * GU_BSTG + bdst[i], bhsrc[i] + (size_t)k0 * FDIM, 16);
            cpa16(smb + GU_BLO + st * GU_BSTG + bdst[i], blsrc[i] + (size_t)k0 * FDIM, 16);
        }
        CP_COMMIT();
    };

    int wid = tid >> 5, lane = tid & 31;
    int wm = (wid >> 1) * 64;          // 4 warps in M, each 64 rows
    int wn = (wid & 1) * 32;
    int gr = lane >> 2, gc = lane & 3;

    uint32_t a_loff[4];
#pragma unroll
    for (int mt = 0; mt < 4; mt++)
        a_loff[mt] = (wm + mt * 16 + (lane & 15)) * GU_AST + (lane >> 4) * 16;
    int bt = lane >> 3;
    uint32_t b_lane = ((bt & 1) * 8 + (lane & 7)) * GU_BST + ((bt >> 1) * 8) * 2;

    float acc[4][8][4];
#pragma unroll
    for (int mt = 0; mt < 4; mt++)
#pragma unroll
        for (int nt = 0; nt < 8; nt++)
#pragma unroll
            for (int j = 0; j < 4; j++) acc[mt][nt][j] = 0.f;

    const int NKC = DDIM / GU_KC;  // 64
    load_stage(0, 0); load_stage(1, 1);

    for (int kc = 0; kc < NKC; kc++) {
        asm volatile("cp.async.wait_group 1;" ::: "memory");
        __syncthreads();
        if (kc + 2 < NKC) load_stage(kc + 2, (kc + 2) % GU_NSTG);

        int st = kc % GU_NSTG;
        uint32_t ah = smb + GU_AHI + st * GU_ASTG;
        uint32_t al = smb + GU_ALO + st * GU_ASTG;
        uint32_t bh = smb + GU_BHI + st * GU_BSTG;
        uint32_t bl = smb + GU_BLO + st * GU_BSTG;

#pragma unroll
        for (int ks = 0; ks < 2; ks++) {
            uint32_t kao = ks * 32;
            uint32_t kbo = ks * 16 * GU_BST;
            uint32_t a_hi[4][4], a_lo[4][4];
#pragma unroll
            for (int mt = 0; mt < 4; mt++) {
                LDSM_X4(a_hi[mt][0], a_hi[mt][1], a_hi[mt][2], a_hi[mt][3], ah + a_loff[mt] + kao);
                LDSM_X4(a_lo[mt][0], a_lo[mt][1], a_lo[mt][2], a_lo[mt][3], al + a_loff[mt] + kao);
            }
#pragma unroll
            for (int half = 0; half < 2; half++) {
#pragma unroll
                for (int p = 0; p < 2; p++) {
                    uint32_t nb2 = (half * 64 + wn + p * 16) * 2;
                    uint32_t bhp[4], blp[4];
                    LDSM_X4T(bhp[0], bhp[1], bhp[2], bhp[3], bh + b_lane + kbo + nb2);
                    LDSM_X4T(blp[0], blp[1], blp[2], blp[3], bl + b_lane + kbo + nb2);
#pragma unroll
                    for (int g = 0; g < 2; g++) {
                        int nt = half * 4 + p * 2 + g;
                        uint32_t* bhx = bhp + g * 2;
                        uint32_t* blx = blp + g * 2;
#pragma unroll
                        for (int mt = 0; mt < 4; mt++) {
                            MMA_BF16(acc[mt][nt], a_hi[mt], blx);
                            MMA_BF16(acc[mt][nt], a_lo[mt], bhx);
                            MMA_BF16(acc[mt][nt], a_hi[mt], bhx);
                        }
                    }
                }
            }
        }
    }

    uint32_t* hh = (uint32_t*)hhi;
    uint32_t* hl = (uint32_t*)hlo;
#pragma unroll
    for (int mt = 0; mt < 4; mt++) {
#pragma unroll
        for (int half = 0; half < 2; half++) {
            int row = wm + mt * 16 + gr + half * 8;
            int tk = toks[row];
            if (tk < 0) continue;
            size_t rb = ((size_t)tk * FDIM + n0 + wn) >> 1;
#pragma unroll
            for (int nt = 0; nt < 4; nt++) {
                float2 v;
                v.x = silu_f(acc[mt][nt][half * 2 + 0]) * acc[mt][nt + 4][half * 2 + 0];
                v.y = silu_f(acc[mt][nt][half * 2 + 1]) * acc[mt][nt + 4][half * 2 + 1];
                uint32_t hi, lo;
                bf16_split2(v, hi, lo);
                size_t idx = rb + ((nt * 8 + gc * 2) >> 1);
                hh[idx] = hi;
                hl[idx] = lo;
            }
        }
    }
}

// ================= down GEMM (M=256 tile, merged routed+shared, atomic epilogue) =================
__global__ void __launch_bounds__(256)
dn_kernel(float* __restrict__ out) {
    int tid = threadIdx.x;
    int e   = blockIdx.z;
    bool sh = (e == 8);
    int cnt = sh ? T_TOK : g_cnt[e];
    int m0  = blockIdx.x * 256;
    if (m0 >= cnt) return;
    int n0  = blockIdx.y * 64;

    const __nv_bfloat16* bdh = sh ? g_wsdhi : g_wdhi + (size_t)e * FDIM * DDIM;
    const __nv_bfloat16* bdl = sh ? g_wsdlo : g_wdlo + (size_t)e * FDIM * DDIM;
    const __nv_bfloat16* hih = sh ? g_hshi : g_hhi;
    const __nv_bfloat16* hil = sh ? g_hslo : g_hlo;

    extern __shared__ char dyn[];
    __shared__ int toks[256];
    {
        int m = m0 + tid;
        toks[tid] = (m < cnt) ? (sh ? m : g_list[e * T_TOK + m]) : -1;
    }
    __syncthreads();

    uint32_t smb = smem_u32(dyn);

    const __nv_bfloat16* ahsrc[4];
    const __nv_bfloat16* alsrc[4];
    int apred[4];
    uint32_t adst[4];
#pragma unroll
    for (int i = 0; i < 4; i++) {
        int s = tid + 256 * i;
        int row = s >> 2, chk = s & 3;
        int tk = toks[row];
        apred[i] = (tk >= 0) ? 16 : 0;
        size_t off = (tk >= 0) ? ((size_t)tk * FDIM + chk * 8) : 0;
        ahsrc[i] = hih + off;
        alsrc[i] = hil + off;
        adst[i]  = row * DN_AST + chk * 16;
    }
    int brow = tid >> 3, bchk = tid & 7;
    size_t boff = (size_t)brow * DDIM + n0 + bchk * 8;
    const __nv_bfloat16* bhsrc = bdh + boff;
    const __nv_bfloat16* blsrc = bdl + boff;
    uint32_t bdst = brow * DN_BST + bchk * 16;

    auto load_stage = [&](int kc, int st) {
        int k0 = kc * DN_KC;
#pragma unroll
        for (int i = 0; i < 4; i++) {
            cpa16(smb + DN_AHI + st * DN_ASTG + adst[i], ahsrc[i] + k0, apred[i]);
            cpa16(smb + DN_ALO + st * DN_ASTG + adst[i], alsrc[i] + k0, apred[i]);
        }
        cpa16(smb + DN_BHI + st * DN_BSTG + bdst, bhsrc + (size_t)k0 * DDIM, 16);
        cpa16(smb + DN_BLO + st * DN_BSTG + bdst, blsrc + (size_t)k0 * DDIM, 16);
        CP_COMMIT();
    };

    int wid = tid >> 5, lane = tid & 31;
    int wm = (wid >> 1) * 64;
    int wn = (wid & 1) * 32;
    int gr = lane >> 2, gc = lane & 3;

    uint32_t a_loff[4];
#pragma unroll
    for (int mt = 0; mt < 4; mt++)
        a_loff[mt] = (wm + mt * 16 + (lane & 15)) * DN_AST + (lane >> 4) * 16;
    int bt = lane >> 3;
    uint32_t b_lane = ((bt & 1) * 8 + (lane & 7)) * DN_BST + ((bt >> 1) * 8) * 2;

    float acc[4][4][4];
#pragma unroll
    for (int mt = 0; mt < 4; mt++)
#pragma unroll
        for (int nt = 0; nt < 4; nt++)
#pragma unroll
            for (int j = 0; j < 4; j++) acc[mt][nt][j] = 0.f;

    const int NKC = FDIM / DN_KC;  // 128
    load_stage(0, 0); load_stage(1, 1);

    for (int kc = 0; kc < NKC; kc++) {
        asm volatile("cp.async.wait_group 1;" ::: "memory");
        __syncthreads();
        if (kc + 2 < NKC) load_stage(kc + 2, (kc + 2) % DN_NSTG);

        int st = kc % DN_NSTG;
        uint32_t ah = smb + DN_AHI + st * DN_ASTG;
        uint32_t al = smb + DN_ALO + st * DN_ASTG;
        uint32_t bh = smb + DN_BHI + st * DN_BSTG;
        uint32_t bl = smb + DN_BLO + st * DN_BSTG;

#pragma unroll
        for (int ks = 0; ks < 2; ks++) {
            uint32_t kao = ks * 32;
            uint32_t kbo = ks * 16 * DN_BST;
            uint32_t a_hi[4][4], a_lo[4][4];
#pragma unroll
            for (int mt = 0; mt < 4; mt++) {
                LDSM_X4(a_hi[mt][0], a_hi[mt][1], a_hi[mt][2], a_hi[mt][3], ah + a_loff[mt] + kao);
                LDSM_X4(a_lo[mt][0], a_lo[mt][1], a_lo[mt][2], a_lo[mt][3], al + a_loff[mt] + kao);
            }
#pragma unroll
            for (int p = 0; p < 2; p++) {
                uint32_t nb2 = (wn + p * 16) * 2;
                uint32_t bhp[4], blp[4];
                LDSM_X4T(bhp[0], bhp[1], bhp[2], bhp[3], bh + b_lane + kbo + nb2);
                LDSM_X4T(blp[0], blp[1], blp[2], blp[3], bl + b_lane + kbo + nb2);
#pragma unroll
                for (int g = 0; g < 2; g++) {
                    int nt = p * 2 + g;
                    uint32_t* bhx = bhp + g * 2;
                    uint32_t* blx = blp + g * 2;
#pragma unroll
                    for (int mt = 0; mt < 4; mt++) {
                        MMA_BF16(acc[mt][nt], a_hi[mt], blx);
                        MMA_BF16(acc[mt][nt], a_lo[mt], bhx);
                        MMA_BF16(acc[mt][nt], a_hi[mt], bhx);
                    }
                }
            }
        }
    }

#pragma unroll
    for (int mt = 0; mt < 4; mt++) {
#pragma unroll
        for (int half = 0; half < 2; half++) {
            int row = wm + mt * 16 + gr + half * 8;
            int tk = toks[row];
            if (tk < 0) continue;
            float wt = sh ? 1.f : g_w[tk];
            float* orow = out + (size_t)tk * DDIM + n0 + wn;
#pragma unroll
            for (int nt = 0; nt < 4; nt++) {
                float* op = orow + nt * 8 + gc * 2;
                atomicAdd(op,     wt * acc[mt][nt][half * 2 + 0]);
                atomicAdd(op + 1, wt * acc[mt][nt][half * 2 + 1]);
            }
        }
    }
}

// ================= host =================
extern "C" void kernel_launch(void* const* d_in, const int* in_sizes, int n_in,
                              void* d_out, int out_size) {
    const float* x   = (const float*)d_in[0];
    const float* rw  = (const float*)d_in[1];
    const float* wg  = (const float*)d_in[2];
    const float* wu  = (const float*)d_in[3];
    const float* wd  = (const float*)d_in[4];
    const float* wsg = (const float*)d_in[5];
    const float* wsu = (const float*)d_in[6];
    const float* wsd = (const float*)d_in[7];
    float* out = (float*)d_out;

    cudaFuncSetAttribute(gu_kernel<true>,  cudaFuncAttributeMaxDynamicSharedMemorySize, SMEM_GU);
    cudaFuncSetAttribute(gu_kernel<false>, cudaFuncAttributeMaxDynamicSharedMemorySize, SMEM_GU);
    cudaFuncSetAttribute(dn_kernel, cudaFuncAttributeMaxDynamicSharedMemorySize, SMEM_DN);

    zero_counts<<<1, 32>>>();
    router_kernel<<<T_TOK / 8, dim3(32, 8)>>>(x, rw);
    scatter_kernel<<<T_TOK / 256, 256>>>();
    convert_x<<<(int)((size_t)T_TOK * DDIM / 2048), 256>>>(x);
    zero_out<<<(int)((size_t)T_TOK * DDIM / 1024), 256>>>((float4*)out);
    convert_wsgu<<<(int)(2 * (size_t)DDIM * FDIM / 2048), 256>>>(wsg, wsu);

    // shared gu (8 m-tiles of 256) + fold(wg|wu): conv ids (y-64)*8+x, y in [64,320)
    gu_kernel<true><<<dim3(8, 320, 1), 256, SMEM_GU>>>(wg, wu);
    // routed gu + fold(wd|wsd): conv ids (y-64)+18*(x+8z), y in [64,82)
    gu_kernel<false><<<dim3(8, 82, NEXP), 256, SMEM_GU>>>(wd, wsd);
    // merged down (z=0..7 routed, 8 shared)
    dn_kernel<<<dim3(8, 32, 9), 256, SMEM_DN>>>(out);
}

// round 17
// speedup vs baseline: 1.3654x; 1.3654x over previous
#include <cuda_runtime.h>
#include <cuda_bf16.h>
#include <math.h>
#include <stdint.h>

#define T_TOK 2048
#define DDIM  2048
#define FDIM  4096
#define NEXP  8

// ---------- gu geometry: KC 32, NSTG 3 ----------
#define GU_NSTG 3
#define GU_KC   32
#define GU_AST  80
#define GU_BST  272
#define GU_ASTG (128 * GU_AST)
#define GU_BSTG (GU_KC * GU_BST)
#define GU_AHI  0
#define GU_ALO  (GU_NSTG * GU_ASTG)
#define GU_BHI  (2 * GU_NSTG * GU_ASTG)
#define GU_BLO  (GU_BHI + GU_NSTG * GU_BSTG)
#define SMEM_GU (GU_BLO + GU_NSTG * GU_BSTG)    // 113664

// ---------- dn geometry: KC 32, NSTG 3 ----------
#define DN_NSTG 3
#define DN_KC   32
#define DN_AST  80
#define DN_BST  144
#define DN_ASTG (128 * DN_AST)
#define DN_BSTG (DN_KC * DN_BST)
#define DN_AHI  0
#define DN_ALO  (DN_NSTG * DN_ASTG)
#define DN_BHI  (2 * DN_NSTG * DN_ASTG)
#define DN_BLO  (DN_BHI + DN_NSTG * DN_BSTG)
#define SMEM_DN (DN_BLO + DN_NSTG * DN_BSTG)    // 89088

#define WGU_ELEMS ((size_t)NEXP * DDIM * FDIM)
#define WD_ELEMS  ((size_t)NEXP * FDIM * DDIM)

// ---- static scratch ----
__device__ int   g_cnt[NEXP];
__device__ int   g_eid[T_TOK];
__device__ float g_w[T_TOK];
__device__ int   g_list[NEXP * T_TOK];
__device__ __align__(16) __nv_bfloat16 g_xhi[(size_t)T_TOK * DDIM];
__device__ __align__(16) __nv_bfloat16 g_xlo[(size_t)T_TOK * DDIM];
__device__ __align__(16) __nv_bfloat16 g_hhi[(size_t)T_TOK * FDIM];
__device__ __align__(16) __nv_bfloat16 g_hlo[(size_t)T_TOK * FDIM];
__device__ __align__(16) __nv_bfloat16 g_hshi[(size_t)T_TOK * FDIM];
__device__ __align__(16) __nv_bfloat16 g_hslo[(size_t)T_TOK * FDIM];
__device__ __align__(16) __nv_bfloat16 g_wghi[(size_t)NEXP * DDIM * FDIM];
__device__ __align__(16) __nv_bfloat16 g_wglo[(size_t)NEXP * DDIM * FDIM];
__device__ __align__(16) __nv_bfloat16 g_wuhi[(size_t)NEXP * DDIM * FDIM];
__device__ __align__(16) __nv_bfloat16 g_wulo[(size_t)NEXP * DDIM * FDIM];
__device__ __align__(16) __nv_bfloat16 g_wdhi[(size_t)NEXP * FDIM * DDIM];
__device__ __align__(16) __nv_bfloat16 g_wdlo[(size_t)NEXP * FDIM * DDIM];
__device__ __align__(16) __nv_bfloat16 g_wsghi[(size_t)DDIM * FDIM];
__device__ __align__(16) __nv_bfloat16 g_wsglo[(size_t)DDIM * FDIM];
__device__ __align__(16) __nv_bfloat16 g_wsuhi[(size_t)DDIM * FDIM];
__device__ __align__(16) __nv_bfloat16 g_wsulo[(size_t)DDIM * FDIM];
__device__ __align__(16) __nv_bfloat16 g_wsdhi[(size_t)FDIM * DDIM];
__device__ __align__(16) __nv_bfloat16 g_wsdlo[(size_t)FDIM * DDIM];

// ---- helpers ----
__device__ __forceinline__ uint32_t smem_u32(const void* p) {
    uint32_t a;
    asm("{ .reg .u64 t; cvta.to.shared.u64 t, %1; cvt.u32.u64 %0, t; }"
        : "=r"(a) : "l"(p));
    return a;
}

__device__ __forceinline__ void cpa16(uint32_t dst, const void* src, int srcsz) {
    asm volatile("cp.async.cg.shared.global [%0], [%1], 16, %2;"
                 :: "r"(dst), "l"(src), "r"(srcsz) : "memory");
}
#define CP_COMMIT() asm volatile("cp.async.commit_group;" ::: "memory")

#define MMA_BF16(d, a, b) \
    asm volatile("mma.sync.aligned.m16n8k16.row.col.f32.bf16.bf16.f32 " \
        "{%0,%1,%2,%3}, {%4,%5,%6,%7}, {%8,%9}, {%0,%1,%2,%3};" \
        : "+f"((d)[0]), "+f"((d)[1]), "+f"((d)[2]), "+f"((d)[3]) \
        : "r"((a)[0]), "r"((a)[1]), "r"((a)[2]), "r"((a)[3]), \
          "r"((b)[0]), "r"((b)[1]))

#define LDSM_X4(r0, r1, r2, r3, addr) \
    asm volatile("ldmatrix.sync.aligned.m8n8.x4.shared.b16 {%0,%1,%2,%3}, [%4];" \
        : "=r"(r0), "=r"(r1), "=r"(r2), "=r"(r3) : "r"(addr))

#define LDSM_X4T(r0, r1, r2, r3, addr) \
    asm volatile("ldmatrix.sync.aligned.m8n8.x4.trans.shared.b16 {%0,%1,%2,%3}, [%4];" \
        : "=r"(r0), "=r"(r1), "=r"(r2), "=r"(r3) : "r"(addr))

__device__ __forceinline__ void bf16_split2(float2 f, uint32_t& hi, uint32_t& lo) {
    uint32_t h;
    asm("cvt.rn.bf16x2.f32 %0, %1, %2;" : "=r"(h) : "f"(f.y), "f"(f.x));
    float hx = __uint_as_float(h << 16);
    float hy = __uint_as_float(h & 0xffff0000u);
    asm("cvt.rn.bf16x2.f32 %0, %1, %2;" : "=r"(lo) : "f"(f.y - hy), "f"(f.x - hx));
    hi = h;
}

__device__ __forceinline__ float silu_f(float g) {
    return g / (1.f + __expf(-g));
}

__device__ __forceinline__ void conv8(const float* src, __nv_bfloat16* dhi,
                                      __nv_bfloat16* dlo, size_t off) {
    float4 a = *(const float4*)(src + off);
    float4 b = *(const float4*)(src + off + 4);
    uint32_t h0, l0, h1, l1, h2, l2, h3, l3;
    bf16_split2(make_float2(a.x, a.y), h0, l0);
    bf16_split2(make_float2(a.z, a.w), h1, l1);
    bf16_split2(make_float2(b.x, b.y), h2, l2);
    bf16_split2(make_float2(b.z, b.w), h3, l3);
    *(uint4*)(dhi + off) = make_uint4(h0, h1, h2, h3);
    *(uint4*)(dlo + off) = make_uint4(l0, l1, l2, l3);
}

// ---- routing / setup ----
__global__ void zero_counts() {
    if (threadIdx.x < NEXP) g_cnt[threadIdx.x] = 0;
}

__global__ void router_kernel(const float* __restrict__ x,
                              const float* __restrict__ rw) {
    int t = blockIdx.x * blockDim.y + threadIdx.y;
    if (t >= T_TOK) return;
    int lane = threadIdx.x;
    float acc[NEXP];
#pragma unroll
    for (int e = 0; e < NEXP; e++) acc[e] = 0.f;
    const float* xr = x + (size_t)t * DDIM;
    for (int d = lane; d < DDIM; d += 32) {
        float xv = xr[d];
        const float4* r = (const float4*)(rw + (size_t)d * NEXP);
        float4 r0 = r[0], r1 = r[1];
        acc[0] += xv * r0.x; acc[1] += xv * r0.y;
        acc[2] += xv * r0.z; acc[3] += xv * r0.w;
        acc[4] += xv * r1.x; acc[5] += xv * r1.y;
        acc[6] += xv * r1.z; acc[7] += xv * r1.w;
    }
#pragma unroll
    for (int off = 16; off > 0; off >>= 1)
#pragma unroll
        for (int e = 0; e < NEXP; e++)
            acc[e] += __shfl_down_sync(0xffffffffu, acc[e], off);
    if (lane == 0) {
        int best = 0; float bv = acc[0];
#pragma unroll
        for (int e = 1; e < NEXP; e++)
            if (acc[e] > bv) { bv = acc[e]; best = e; }
        g_eid[t] = best;
        g_w[t]   = 1.f / (1.f + expf(-bv));
    }
}

__global__ void scatter_kernel() {
    int t = blockIdx.x * blockDim.x + threadIdx.x;
    if (t < T_TOK) {
        int e = g_eid[t];
        int p = atomicAdd(&g_cnt[e], 1);
        g_list[e * T_TOK + p] = t;
    }
}

// merged prefix: convert x (2048 blocks) | convert wsg/wsu (8192) | zero out (4096)
__global__ void __launch_bounds__(256)
setup_kernel(const float* __restrict__ x,
             const float* __restrict__ wsg,
             const float* __restrict__ wsu,
             float4* __restrict__ out) {
    int b = blockIdx.x;
    if (b < 2048) {
        size_t off = ((size_t)b * 256 + threadIdx.x) * 8;
        conv8(x, g_xhi, g_xlo, off);
    } else if (b < 10240) {
        size_t off = ((size_t)(b - 2048) * 256 + threadIdx.x) * 8;
        const size_t N = (size_t)DDIM * FDIM;
        if (off < N) conv8(wsg, g_wsghi, g_wsglo, off);
        else         conv8(wsu, g_wsuhi, g_wsulo, off - N);
    } else {
        // zero out: 4096 blocks x 256 thr x 16B = 16 MB = T_TOK*DDIM*4B
        out[(size_t)(b - 10240) * 256 + threadIdx.x] = make_float4(0.f, 0.f, 0.f, 0.f);
    }
}

// ================= gate+up GEMM =================
// SHARED: shared-expert gemm; fold converts wg|wu (2048 blocks).
// Routed: routed gemm; fold converts wd|wsd (1152 blocks).
template<bool SHARED>
__global__ void __launch_bounds__(256, 2)
gu_kernel(const float* __restrict__ cv0, const float* __restrict__ cv1) {
    int tid = threadIdx.x;

    if (blockIdx.y >= 64) {
        if (SHARED) {
            int cid = (blockIdx.y - 64) * 16 + blockIdx.x;      // 0..2047
            size_t base = (size_t)cid * 65536;
#pragma unroll 4
            for (int it = 0; it < 32; it++) {
                size_t e0 = base + (size_t)it * 2048 + (size_t)tid * 8;
                if (e0 < WGU_ELEMS) conv8(cv0, g_wghi, g_wglo, e0);
                else                conv8(cv1, g_wuhi, g_wulo, e0 - WGU_ELEMS);
            }
        } else {
            int cid = (blockIdx.y - 64) + 9 * (blockIdx.x + 16 * blockIdx.z); // 0..1151
            size_t base = (size_t)cid * 65536;
#pragma unroll 4
            for (int it = 0; it < 32; it++) {
                size_t e0 = base + (size_t)it * 2048 + (size_t)tid * 8;
                if (e0 < WD_ELEMS) conv8(cv0, g_wdhi, g_wdlo, e0);
                else               conv8(cv1, g_wsdhi, g_wsdlo, e0 - WD_ELEMS);
            }
        }
        return;
    }

    int e   = SHARED ? 0 : blockIdx.z;
    int cnt = SHARED ? T_TOK : g_cnt[e];
    int m0  = blockIdx.x * 128;
    if (m0 >= cnt) return;
    int n0  = blockIdx.y * 64;

    const __nv_bfloat16* bgh = SHARED ? g_wsghi : g_wghi + (size_t)e * DDIM * FDIM;
    const __nv_bfloat16* bgl = SHARED ? g_wsglo : g_wglo + (size_t)e * DDIM * FDIM;
    const __nv_bfloat16* buh = SHARED ? g_wsuhi : g_wuhi + (size_t)e * DDIM * FDIM;
    const __nv_bfloat16* bul = SHARED ? g_wsulo : g_wulo + (size_t)e * DDIM * FDIM;
    __nv_bfloat16* hhi = SHARED ? g_hshi : g_hhi;
    __nv_bfloat16* hlo = SHARED ? g_hslo : g_hlo;

    extern __shared__ char dyn[];
    __shared__ int toks[128];
    if (tid < 128) {
        int m = m0 + tid;
        toks[tid] = (m < cnt) ? (SHARED ? m : g_list[e * T_TOK + m]) : -1;
    }
    __syncthreads();

    uint32_t smb = smem_u32(dyn);

    const __nv_bfloat16* ahsrc[2];
    const __nv_bfloat16* alsrc[2];
    int apred[2];
    uint32_t adst[2];
#pragma unroll
    for (int i = 0; i < 2; i++) {
        int s = tid + 256 * i;
        int row = s >> 2, chk = s & 3;
        int tk = toks[row];
        apred[i] = (tk >= 0) ? 16 : 0;
        size_t off = (tk >= 0) ? ((size_t)tk * DDIM + chk * 8) : 0;
        ahsrc[i] = g_xhi + off;
        alsrc[i] = g_xlo + off;
        adst[i]  = row * GU_AST + chk * 16;
    }
    const __nv_bfloat16* bhsrc[2];
    const __nv_bfloat16* blsrc[2];
    uint32_t bdst[2];
#pragma unroll
    for (int i = 0; i < 2; i++) {
        int s = tid + 256 * i;
        int brow = s >> 4, bchk = s & 15;
        size_t boff = (size_t)brow * FDIM + n0 + (bchk & 7) * 8;
        bhsrc[i] = ((bchk < 8) ? bgh : buh) + boff;
        blsrc[i] = ((bchk < 8) ? bgl : bul) + boff;
        bdst[i]  = brow * GU_BST + bchk * 16;
    }

    auto load_stage = [&](int kc, int st) {
        int k0 = kc * GU_KC;
#pragma unroll
        for (int i = 0; i < 2; i++) {
            cpa16(smb + GU_AHI + st * GU_ASTG + adst[i], ahsrc[i] + k0, apred[i]);
            cpa16(smb + GU_ALO + st * GU_ASTG + adst[i], alsrc[i] + k0, apred[i]);
        }
#pragma unroll
        for (int i = 0; i < 2; i++) {
            cpa16(smb + GU_BHI + st * GU_BSTG + bdst[i], bhsrc[i] + (size_t)k0 * FDIM, 16);
            cpa16(smb + GU_BLO + st * GU_BSTG + bdst[i], blsrc[i] + (size_t)k0 * FDIM, 16);
        }
        CP_COMMIT();
    };

    int wid = tid >> 5, lane = tid & 31;
    int wm = (wid >> 1) * 32;
    int wn = (wid & 1) * 32;
    int gr = lane >> 2, gc = lane & 3;

    uint32_t a_loff[2];
#pragma unroll
    for (int mt = 0; mt < 2; mt++)
        a_loff[mt] = (wm + mt * 16 + (lane & 15)) * GU_AST + (lane >> 4) * 16;
    int bt = lane >> 3;
    uint32_t b_lane = ((bt & 1) * 8 + (lane & 7)) * GU_BST + ((bt >> 1) * 8) * 2;

    float acc[2][8][4];
#pragma unroll
    for (int mt = 0; mt < 2; mt++)
#pragma unroll
        for (int nt = 0; nt < 8; nt++)
#pragma unroll
            for (int j = 0; j < 4; j++) acc[mt][nt][j] = 0.f;

    const int NKC = DDIM / GU_KC;  // 64
    load_stage(0, 0); load_stage(1, 1);

    for (int kc = 0; kc < NKC; kc++) {
        asm volatile("cp.async.wait_group 1;" ::: "memory");
        __syncthreads();
        if (kc + 2 < NKC) load_stage(kc + 2, (kc + 2) % GU_NSTG);

        int st = kc % GU_NSTG;
        uint32_t ah = smb + GU_AHI + st * GU_ASTG;
        uint32_t al = smb + GU_ALO + st * GU_ASTG;
        uint32_t bh = smb + GU_BHI + st * GU_BSTG;
        uint32_t bl = smb + GU_BLO + st * GU_BSTG;

#pragma unroll
        for (int ks = 0; ks < 2; ks++) {
            uint32_t kao = ks * 32;
            uint32_t kbo = ks * 16 * GU_BST;
            uint32_t a_hi[2][4], a_lo[2][4];
#pragma unroll
            for (int mt = 0; mt < 2; mt++) {
                LDSM_X4(a_hi[mt][0], a_hi[mt][1], a_hi[mt][2], a_hi[mt][3], ah + a_loff[mt] + kao);
                LDSM_X4(a_lo[mt][0], a_lo[mt][1], a_lo[mt][2], a_lo[mt][3], al + a_loff[mt] + kao);
            }
#pragma unroll
            for (int half = 0; half < 2; half++) {
#pragma unroll
                for (int p = 0; p < 2; p++) {
                    uint32_t nb2 = (half * 64 + wn + p * 16) * 2;
                    uint32_t bhp[4], blp[4];
                    LDSM_X4T(bhp[0], bhp[1], bhp[2], bhp[3], bh + b_lane + kbo + nb2);
                    LDSM_X4T(blp[0], blp[1], blp[2], blp[3], bl + b_lane + kbo + nb2);
#pragma unroll
                    for (int g = 0; g < 2; g++) {
                        int nt = half * 4 + p * 2 + g;
                        uint32_t* bhx = bhp + g * 2;
                        uint32_t* blx = blp + g * 2;
#pragma unroll
                        for (int mt = 0; mt < 2; mt++) {
                            MMA_BF16(acc[mt][nt], a_hi[mt], blx);
                            MMA_BF16(acc[mt][nt], a_lo[mt], bhx);
                            MMA_BF16(acc[mt][nt], a_hi[mt], bhx);
                        }
                    }
                }
            }
        }
    }

    uint32_t* hh = (uint32_t*)hhi;
    uint32_t* hl = (uint32_t*)hlo;
#pragma unroll
    for (int mt = 0; mt < 2; mt++) {
#pragma unroll
        for (int half = 0; half < 2; half++) {
            int row = wm + mt * 16 + gr + half * 8;
            int tk = toks[row];
            if (tk < 0) continue;
            size_t rb = ((size_t)tk * FDIM + n0 + wn) >> 1;
#pragma unroll
            for (int nt = 0; nt < 4; nt++) {
                float2 v;
                v.x = silu_f(acc[mt][nt][half * 2 + 0]) * acc[mt][nt + 4][half * 2 + 0];
                v.y = silu_f(acc[mt][nt][half * 2 + 1]) * acc[mt][nt + 4][half * 2 + 1];
                uint32_t hi, lo;
                bf16_split2(v, hi, lo);
                size_t idx = rb + ((nt * 8 + gc * 2) >> 1);
                hh[idx] = hi;
                hl[idx] = lo;
            }
        }
    }
}

// ================= down GEMM (merged routed+shared, atomic epilogue) =================
__global__ void __launch_bounds__(256, 2)
dn_kernel(float* __restrict__ out) {
    int tid = threadIdx.x;
    int e   = blockIdx.z;
    bool sh = (e == 8);
    int cnt = sh ? T_TOK : g_cnt[e];
    int m0  = blockIdx.x * 128;
    if (m0 >= cnt) return;
    int n0  = blockIdx.y * 64;

    const __nv_bfloat16* bdh = sh ? g_wsdhi : g_wdhi + (size_t)e * FDIM * DDIM;
    const __nv_bfloat16* bdl = sh ? g_wsdlo : g_wdlo + (size_t)e * FDIM * DDIM;
    const __nv_bfloat16* hih = sh ? g_hshi : g_hhi;
    const __nv_bfloat16* hil = sh ? g_hslo : g_hlo;

    extern __shared__ char dyn[];
    __shared__ int toks[128];
    if (tid < 128) {
        int m = m0 + tid;
        toks[tid] = (m < cnt) ? (sh ? m : g_list[e * T_TOK + m]) : -1;
    }
    __syncthreads();

    uint32_t smb = smem_u32(dyn);

    const __nv_bfloat16* ahsrc[2];
    const __nv_bfloat16* alsrc[2];
    int apred[2];
    uint32_t adst[2];
#pragma unroll
    for (int i = 0; i < 2; i++) {
        int s = tid + 256 * i;
        int row = s >> 2, chk = s & 3;
        int tk = toks[row];
        apred[i] = (tk >= 0) ? 16 : 0;
        size_t off = (tk >= 0) ? ((size_t)tk * FDIM + chk * 8) : 0;
        ahsrc[i] = hih + off;
        alsrc[i] = hil + off;
        adst[i]  = row * DN_AST + chk * 16;
    }
    int brow = tid >> 3, bchk = tid & 7;
    size_t boff = (size_t)brow * DDIM + n0 + bchk * 8;
    const __nv_bfloat16* bhsrc = bdh + boff;
    const __nv_bfloat16* blsrc = bdl + boff;
    uint32_t bdst = brow * DN_BST + bchk * 16;

    auto load_stage = [&](int kc, int st) {
        int k0 = kc * DN_KC;
#pragma unroll
        for (int i = 0; i < 2; i++) {
            cpa16(smb + DN_AHI + st * DN_ASTG + adst[i], ahsrc[i] + k0, apred[i]);
            cpa16(smb + DN_ALO + st * DN_ASTG + adst[i], alsrc[i] + k0, apred[i]);
        }
        cpa16(smb + DN_BHI + st * DN_BSTG + bdst, bhsrc + (size_t)k0 * DDIM, 16);
        cpa16(smb + DN_BLO + st * DN_BSTG + bdst, blsrc + (size_t)k0 * DDIM, 16);
        CP_COMMIT();
    };

    int wid = tid >> 5, lane = tid & 31;
    int wm = (wid >> 1) * 32;
    int wn = (wid & 1) * 32;
    int gr = lane >> 2, gc = lane & 3;

    uint32_t a_loff[2];
#pragma unroll
    for (int mt = 0; mt < 2; mt++)
        a_loff[mt] = (wm + mt * 16 + (lane & 15)) * DN_AST + (lane >> 4) * 16;
    int bt = lane >> 3;
    uint32_t b_lane = ((bt & 1) * 8 + (lane & 7)) * DN_BST + ((bt >> 1) * 8) * 2;

    float acc[2][4][4];
#pragma unroll
    for (int mt = 0; mt < 2; mt++)
#pragma unroll
        for (int nt = 0; nt < 4; nt++)
#pragma unroll
            for (int j = 0; j < 4; j++) acc[mt][nt][j] = 0.f;

    const int NKC = FDIM / DN_KC;  // 128
    load_stage(0, 0); load_stage(1, 1);

    for (int kc = 0; kc < NKC; kc++) {
        asm volatile("cp.async.wait_group 1;" ::: "memory");
        __syncthreads();
        if (kc + 2 < NKC) load_stage(kc + 2, (kc + 2) % DN_NSTG);

        int st = kc % DN_NSTG;
        uint32_t ah = smb + DN_AHI + st * DN_ASTG;
        uint32_t al = smb + DN_ALO + st * DN_ASTG;
        uint32_t bh = smb + DN_BHI + st * DN_BSTG;
        uint32_t bl = smb + DN_BLO + st * DN_BSTG;

#pragma unroll
        for (int ks = 0; ks < 2; ks++) {
            uint32_t kao = ks * 32;
            uint32_t kbo = ks * 16 * DN_BST;
            uint32_t a_hi[2][4], a_lo[2][4];
#pragma unroll
            for (int mt = 0; mt < 2; mt++) {
                LDSM_X4(a_hi[mt][0], a_hi[mt][1], a_hi[mt][2], a_hi[mt][3], ah + a_loff[mt] + kao);
                LDSM_X4(a_lo[mt][0], a_lo[mt][1], a_lo[mt][2], a_lo[mt][3], al + a_loff[mt] + kao);
            }
#pragma unroll
            for (int p = 0; p < 2; p++) {
                uint32_t nb2 = (wn + p * 16) * 2;
                uint32_t bhp[4], blp[4];
                LDSM_X4T(bhp[0], bhp[1], bhp[2], bhp[3], bh + b_lane + kbo + nb2);
                LDSM_X4T(blp[0], blp[1], blp[2], blp[3], bl + b_lane + kbo + nb2);
#pragma unroll
                for (int g = 0; g < 2; g++) {
                    int nt = p * 2 + g;
                    uint32_t* bhx = bhp + g * 2;
                    uint32_t* blx = blp + g * 2;
#pragma unroll
                    for (int mt = 0; mt < 2; mt++) {
                        MMA_BF16(acc[mt][nt], a_hi[mt], blx);
                        MMA_BF16(acc[mt][nt], a_lo[mt], bhx);
                        MMA_BF16(acc[mt][nt], a_hi[mt], bhx);
                    }
                }
            }
        }
    }

#pragma unroll
    for (int mt = 0; mt < 2; mt++) {
#pragma unroll
        for (int half = 0; half < 2; half++) {
            int row = wm + mt * 16 + gr + half * 8;
            int tk = toks[row];
            if (tk < 0) continue;
            float wt = sh ? 1.f : g_w[tk];
            float* orow = out + (size_t)tk * DDIM + n0 + wn;
#pragma unroll
            for (int nt = 0; nt < 4; nt++) {
                float* op = orow + nt * 8 + gc * 2;
                atomicAdd(op,     wt * acc[mt][nt][half * 2 + 0]);
                atomicAdd(op + 1, wt * acc[mt][nt][half * 2 + 1]);
            }
        }
    }
}

// ================= host =================
extern "C" void kernel_launch(void* const* d_in, const int* in_sizes, int n_in,
                              void* d_out, int out_size) {
    const float* x   = (const float*)d_in[0];
    const float* rw  = (const float*)d_in[1];
    const float* wg  = (const float*)d_in[2];
    const float* wu  = (const float*)d_in[3];
    const float* wd  = (const float*)d_in[4];
    const float* wsg = (const float*)d_in[5];
    const float* wsu = (const float*)d_in[6];
    const float* wsd = (const float*)d_in[7];
    float* out = (float*)d_out;

    cudaFuncSetAttribute(gu_kernel<true>,  cudaFuncAttributeMaxDynamicSharedMemorySize, SMEM_GU);
    cudaFuncSetAttribute(gu_kernel<false>, cudaFuncAttributeMaxDynamicSharedMemorySize, SMEM_GU);
    cudaFuncSetAttribute(dn_kernel, cudaFuncAttributeMaxDynamicSharedMemorySize, SMEM_DN);

    zero_counts<<<1, 32>>>();
    router_kernel<<<T_TOK / 8, dim3(32, 8)>>>(x, rw);
    scatter_kernel<<<T_TOK / 256, 256>>>();
    // merged prefix: convert x (2048) | convert wsg/wsu (8192) | zero out (4096)
    setup_kernel<<<14336, 256>>>(x, wsg, wsu, (float4*)out);

    gu_kernel<true><<<dim3(16, 192, 1), 256, SMEM_GU>>>(wg, wu);
    gu_kernel<false><<<dim3(16, 73, NEXP), 256, SMEM_GU>>>(wd, wsd);
    dn_kernel<<<dim3(16, 32, 9), 256, SMEM_DN>>>(out);
}